// round 3
// baseline (speedup 1.0000x reference)
#include <cuda_runtime.h>
#include <cstdint>
#include <cstddef>

typedef unsigned long long ull;

#define BB 512
#define TT 1024
#define INDIM 32
#define HH 128
#define GG 512            // 4*H
#define DLL 256
#define OUTD 32
#define M_TOT (BB*TT)     // 524288

#define KSM 96            // Whh k-rows kept in smem (interleaved)
#define KTL 32            // tail k-rows in registers (8 per quarter)
// smem: weights 96*512*4 + h 512*4 + exchange 4*3*128*16
#define LSTM_SMEM (KSM*GG*4 + 512*4 + 4*3*128*16)   // 223232 bytes

#define GLD 132
#define GEMM_SMEM_MAX (2 * 128 * GLD * 4)       // 135168 bytes (K=128 case)

// -------- device scratch (static; no runtime allocation) --------
__device__ float g_xg[(size_t)M_TOT * GG];       // pre-gates for current layer
__device__ float g_h0[(size_t)M_TOT * HH];       // layer-0 hidden sequence
__device__ float g_hlast[BB * HH];
__device__ float g_WT0[HH * GG];                 // Whh0 interleaved [k][j][gate]
__device__ float g_WT1[HH * GG];

// ---------------- f32x2 helpers ----------------
__device__ __forceinline__ ull fma2(ull a, ull b, ull c) {
    ull d;
    asm("fma.rn.f32x2 %0, %1, %2, %3;" : "=l"(d) : "l"(a), "l"(b), "l"(c));
    return d;
}
__device__ __forceinline__ ull add2(ull a, ull b) {
    ull d;
    asm("add.rn.f32x2 %0, %1, %2;" : "=l"(d) : "l"(a), "l"(b));
    return d;
}
__device__ __forceinline__ ull pack2(float x, float y) {
    ull d;
    asm("mov.b64 %0, {%1, %2};" : "=l"(d) : "r"(__float_as_uint(x)), "r"(__float_as_uint(y)));
    return d;
}
__device__ __forceinline__ ull dup2(float x) {
    unsigned v = __float_as_uint(x);
    ull d;
    asm("mov.b64 %0, {%1, %1};" : "=l"(d) : "r"(v));
    return d;
}
__device__ __forceinline__ void unpack2(ull v, float& x, float& y) {
    unsigned a, b;
    asm("mov.b64 {%0, %1}, %2;" : "=r"(a), "=r"(b) : "l"(v));
    x = __uint_as_float(a);
    y = __uint_as_float(b);
}

__device__ __forceinline__ float sigf(float x)  { return __fdividef(1.0f, 1.0f + __expf(-x)); }
__device__ __forceinline__ float tanhx(float x) { return __fdividef(2.0f, 1.0f + __expf(-2.0f * x)) - 1.0f; }

// -------- interleave Whh [512][128] -> WTI [128][128][4]: WTI[k][j][q] = Whh[q*128+j][k] --------
__global__ void prep_whh(const float* __restrict__ W, float* __restrict__ WTI) {
    int idx = blockIdx.x * 256 + threadIdx.x;    // 65536 total
    if (idx < HH * GG) {
        int k = idx >> 9;
        int rem = idx & 511;
        int jj = rem >> 2;
        int q = rem & 3;
        WTI[idx] = W[(q * HH + jj) * HH + k];
    }
}

// -------- 128x128-tile fp32 GEMM (FFMA2): C[m][n] = sum_k A[m][k]*W[n][k] + ba[n] + bb[n] --------
__global__ void __launch_bounds__(256) gemm2_kernel(
    const float* __restrict__ A, const float* __restrict__ W,
    const float* __restrict__ ba, const float* __restrict__ bb,
    float* __restrict__ C, int M, int N, int K)
{
    extern __shared__ float sm[];
    float* sA = sm;                 // [K][GLD]
    float* sB = sm + K * GLD;       // [K][GLD]
    const int tid = threadIdx.x;
    const int m0 = blockIdx.x * 128;
    const int n0 = blockIdx.y * 128;
    const int kv = K >> 2;

    for (int idx = tid; idx < 128 * kv; idx += 256) {
        int m = idx / kv;
        int kq = (idx - m * kv) << 2;
        float4 v = *(const float4*)(A + (size_t)(m0 + m) * K + kq);
        sA[(kq + 0) * GLD + m] = v.x;
        sA[(kq + 1) * GLD + m] = v.y;
        sA[(kq + 2) * GLD + m] = v.z;
        sA[(kq + 3) * GLD + m] = v.w;
    }
    for (int idx = tid; idx < 128 * kv; idx += 256) {
        int n = idx / kv;
        int kq = (idx - n * kv) << 2;
        float4 v = *(const float4*)(W + (size_t)(n0 + n) * K + kq);
        sB[(kq + 0) * GLD + n] = v.x;
        sB[(kq + 1) * GLD + n] = v.y;
        sB[(kq + 2) * GLD + n] = v.z;
        sB[(kq + 3) * GLD + n] = v.w;
    }
    __syncthreads();

    const int ty = tid >> 4;          // 0..15
    const int tx = tid & 15;          // 0..15
    const int ra = ty * 4;
    const int rb = 64 + ty * 4;
    const int c0 = tx * 4;
    const int c1 = 64 + tx * 4;

    ull acc[8][4];
    #pragma unroll
    for (int i = 0; i < 8; i++)
        #pragma unroll
        for (int p = 0; p < 4; p++) acc[i][p] = 0ULL;

    #pragma unroll 4
    for (int k = 0; k < K; k++) {
        float4 a0 = *(const float4*)(sA + k * GLD + ra);
        float4 a1 = *(const float4*)(sA + k * GLD + rb);
        float4 b0 = *(const float4*)(sB + k * GLD + c0);
        float4 b1 = *(const float4*)(sB + k * GLD + c1);
        ull bp0 = pack2(b0.x, b0.y), bp1 = pack2(b0.z, b0.w);
        ull bp2 = pack2(b1.x, b1.y), bp3 = pack2(b1.z, b1.w);
        float av[8] = {a0.x, a0.y, a0.z, a0.w, a1.x, a1.y, a1.z, a1.w};
        #pragma unroll
        for (int i = 0; i < 8; i++) {
            ull d = dup2(av[i]);
            acc[i][0] = fma2(d, bp0, acc[i][0]);
            acc[i][1] = fma2(d, bp1, acc[i][1]);
            acc[i][2] = fma2(d, bp2, acc[i][2]);
            acc[i][3] = fma2(d, bp3, acc[i][3]);
        }
    }

    ull bias0 = pack2(ba[n0 + c0 + 0] + bb[n0 + c0 + 0], ba[n0 + c0 + 1] + bb[n0 + c0 + 1]);
    ull bias1 = pack2(ba[n0 + c0 + 2] + bb[n0 + c0 + 2], ba[n0 + c0 + 3] + bb[n0 + c0 + 3]);
    ull bias2 = pack2(ba[n0 + c1 + 0] + bb[n0 + c1 + 0], ba[n0 + c1 + 1] + bb[n0 + c1 + 1]);
    ull bias3 = pack2(ba[n0 + c1 + 2] + bb[n0 + c1 + 2], ba[n0 + c1 + 3] + bb[n0 + c1 + 3]);

    #pragma unroll
    for (int i = 0; i < 8; i++) {
        int row = m0 + (i < 4 ? ra + i : rb + i - 4);
        ull* p0 = (ull*)(C + (size_t)row * N + n0 + c0);
        p0[0] = add2(acc[i][0], bias0);
        p0[1] = add2(acc[i][1], bias1);
        ull* p1 = (ull*)(C + (size_t)row * N + n0 + c1);
        p1[0] = add2(acc[i][2], bias2);
        p1[1] = add2(acc[i][3], bias3);
    }
}

// -------- LSTM recurrence: 4 rows/CTA, 512 threads, 4-way k split, FFMA2 --------
// quarter u owns batch row (b0+u)'s activation; computes partial gate sums for
// all 4 rows over k in [u*24, u*24+24) (smem) and [96+u*8, 96+u*8+8) (regs).

#define KSTEP(C, KD) { \
    ulonglong2 w = *(const ulonglong2*)(sw16 + ((size_t)(k + KD) * 128 + j)); \
    ull d0 = dup2(h0.C), d1 = dup2(h1.C), d2 = dup2(h2.C), d3 = dup2(h3.C); \
    a00 = fma2(d0, w.x, a00); a01 = fma2(d0, w.y, a01); \
    a10 = fma2(d1, w.x, a10); a11 = fma2(d1, w.y, a11); \
    a20 = fma2(d2, w.x, a20); a21 = fma2(d2, w.y, a21); \
    a30 = fma2(d3, w.x, a30); a31 = fma2(d3, w.y, a31); }

#define TSTEP(IDX, C) { \
    ulonglong2 w = wt[IDX]; \
    ull d0 = dup2(h0.C), d1 = dup2(h1.C), d2 = dup2(h2.C), d3 = dup2(h3.C); \
    a00 = fma2(d0, w.x, a00); a01 = fma2(d0, w.y, a01); \
    a10 = fma2(d1, w.x, a10); a11 = fma2(d1, w.y, a11); \
    a20 = fma2(d2, w.x, a20); a21 = fma2(d2, w.y, a21); \
    a30 = fma2(d3, w.x, a30); a31 = fma2(d3, w.y, a31); }

__global__ void __launch_bounds__(512, 1) lstm_layer_kernel(
    const float* __restrict__ xg,      // [M_TOT][512] pre-gates, row = b*T + t
    const float* __restrict__ WTI,     // [128][128][4] interleaved Whh
    float* __restrict__ hout,          // [M_TOT][128] or nullptr
    float* __restrict__ hlast)         // [B][128]     or nullptr
{
    extern __shared__ float sm[];
    float* sW = sm;                                    // [96][512] interleaved
    float* sh = sm + KSM * GG;                         // [4][128] hidden state
    ulonglong2* sxv = (ulonglong2*)(sm + KSM * GG + 512);  // [4 rows][3 partials][128]

    const int tid = threadIdx.x;
    const int j = tid & 127;
    const int u = tid >> 7;              // quarter 0..3
    const int b0 = blockIdx.x * 4;

    const ulonglong2* sw16 = (const ulonglong2*)sW;

    // load weights k in [0, KSM) into smem
    {
        const float4* g4 = (const float4*)WTI;
        float4* s4 = (float4*)sW;
        for (int i = tid; i < KSM * 128; i += 512) s4[i] = g4[i];
    }
    // tail weights k in [96 + u*8, 96 + u*8 + 8) in registers
    ulonglong2 wt[8];
    {
        int kt = KSM + u * 8;
        #pragma unroll
        for (int i = 0; i < 8; i++)
            wt[i] = *(const ulonglong2*)(WTI + (size_t)(kt + i) * GG + j * 4);
    }
    sh[tid & 511] = 0.0f;

    const int klo = u * 24;            // smem k range start (24 rows)
    const int kt0 = KSM + u * 8;       // reg tail k start

    // own row pre-gate stream
    const size_t xbase = ((size_t)(b0 + u)) * TT * GG + j;
    float* houtP = hout ? hout + ((size_t)(b0 + u)) * TT * HH + j : (float*)0;

    ull xc0 = pack2(xg[xbase], xg[xbase + 128]);
    ull xc1 = pack2(xg[xbase + 256], xg[xbase + 384]);

    float cc = 0.0f, hh = 0.0f;
    __syncthreads();

    for (int t = 0; t < TT; t++) {
        ull a00 = 0, a01 = 0, a10 = 0, a11 = 0, a20 = 0, a21 = 0, a30 = 0, a31 = 0;

        // prefetch next step's own-row pre-gates
        float xn0 = 0, xn1 = 0, xn2 = 0, xn3 = 0;
        if (t + 1 < TT) {
            size_t o = xbase + (size_t)(t + 1) * GG;
            xn0 = xg[o]; xn1 = xg[o + 128]; xn2 = xg[o + 256]; xn3 = xg[o + 384];
        }

        // smem k range: 24 rows (6 groups of 4)
        #pragma unroll
        for (int qi = 0; qi < 6; qi++) {
            int k = klo + qi * 4;
            float4 h0 = *(const float4*)(sh + k);
            float4 h1 = *(const float4*)(sh + 128 + k);
            float4 h2 = *(const float4*)(sh + 256 + k);
            float4 h3 = *(const float4*)(sh + 384 + k);
            KSTEP(x, 0) KSTEP(y, 1) KSTEP(z, 2) KSTEP(w, 3)
        }
        // register tail: 8 k rows (2 groups of 4)
        {
            int k = kt0;
            float4 h0 = *(const float4*)(sh + k);
            float4 h1 = *(const float4*)(sh + 128 + k);
            float4 h2 = *(const float4*)(sh + 256 + k);
            float4 h3 = *(const float4*)(sh + 384 + k);
            TSTEP(0, x) TSTEP(1, y) TSTEP(2, z) TSTEP(3, w)
            k += 4;
            h0 = *(const float4*)(sh + k);
            h1 = *(const float4*)(sh + 128 + k);
            h2 = *(const float4*)(sh + 256 + k);
            h3 = *(const float4*)(sh + 384 + k);
            TSTEP(4, x) TSTEP(5, y) TSTEP(6, z) TSTEP(7, w)
        }

        // write partials for the 3 non-own rows; slot = u - (u > r)
        {
            ulonglong2 v;
            if (u != 0) { v.x = a00; v.y = a01; sxv[(0 * 3 + (u - 1)) * 128 + j] = v; }
            if (u != 1) { v.x = a10; v.y = a11; sxv[(1 * 3 + ((u == 0) ? 0 : u - 1)) * 128 + j] = v; }
            if (u != 2) { v.x = a20; v.y = a21; sxv[(2 * 3 + ((u == 3) ? 2 : u)) * 128 + j] = v; }
            if (u != 3) { v.x = a30; v.y = a31; sxv[(3 * 3 + u) * 128 + j] = v; }
        }
        __syncthreads();
        {
            // own row: own partial + 3 foreign partials + pre-gates
            ull o0, o1;
            if      (u == 0) { o0 = a00; o1 = a01; }
            else if (u == 1) { o0 = a10; o1 = a11; }
            else if (u == 2) { o0 = a20; o1 = a21; }
            else             { o0 = a30; o1 = a31; }
            int base = u * 3 * 128 + j;
            ulonglong2 p0 = sxv[base];
            ulonglong2 p1 = sxv[base + 128];
            ulonglong2 p2 = sxv[base + 256];
            ull t0 = add2(add2(o0, xc0), add2(p0.x, add2(p1.x, p2.x)));
            ull t1 = add2(add2(o1, xc1), add2(p0.y, add2(p1.y, p2.y)));

            float gi, gf, gg2, go;
            unpack2(t0, gi, gf);
            unpack2(t1, gg2, go);
            float ii = sigf(gi), ff = sigf(gf), g = tanhx(gg2), oo = sigf(go);
            cc = ff * cc + ii * g;
            hh = oo * tanhx(cc);

            sh[u * 128 + j] = hh;
            if (hout) houtP[(size_t)t * HH] = hh;
        }
        xc0 = pack2(xn0, xn1);
        xc1 = pack2(xn2, xn3);
        __syncthreads();
    }

    if (hlast) hlast[(b0 + u) * HH + j] = hh;
}

// -------- MLP head: y = celu(celu(last @ W1^T + b1) @ W2^T + b2) --------
__device__ __forceinline__ float celuf(float x) { return x > 0.0f ? x : expm1f(x); }

__global__ void __launch_bounds__(256) head_kernel(
    const float* __restrict__ hlast,
    const float* __restrict__ W1, const float* __restrict__ b1,
    const float* __restrict__ W2, const float* __restrict__ b2,
    float* __restrict__ out)
{
    const int b = blockIdx.x;
    const int tid = threadIdx.x;
    __shared__ float sl[HH];
    __shared__ float sy[DLL];

    if (tid < HH) sl[tid] = hlast[b * HH + tid];
    __syncthreads();

    float s = b1[tid];
    const float* w = W1 + (size_t)tid * HH;
    #pragma unroll 8
    for (int k = 0; k < HH; k++) s += sl[k] * w[k];
    sy[tid] = celuf(s);
    __syncthreads();

    if (tid < OUTD) {
        float s2 = b2[tid];
        const float* w2 = W2 + (size_t)tid * DLL;
        #pragma unroll 8
        for (int k = 0; k < DLL; k++) s2 += sy[k] * w2[k];
        out[b * OUTD + tid] = celuf(s2);
    }
}

__global__ void zero_tail(float* __restrict__ p, int n) {
    int i = blockIdx.x * 256 + threadIdx.x;
    if (i < n) p[i] = 0.0f;
}

// -------- launch --------
extern "C" void kernel_launch(void* const* d_in, const int* in_sizes, int n_in,
                              void* d_out, int out_size)
{
    const float* x    = (const float*)d_in[0];
    const float* Wih0 = (const float*)d_in[1];
    const float* Whh0 = (const float*)d_in[2];
    const float* bih0 = (const float*)d_in[3];
    const float* bhh0 = (const float*)d_in[4];
    const float* Wih1 = (const float*)d_in[5];
    const float* Whh1 = (const float*)d_in[6];
    const float* bih1 = (const float*)d_in[7];
    const float* bhh1 = (const float*)d_in[8];
    const float* W1   = (const float*)d_in[9];
    const float* b1   = (const float*)d_in[10];
    const float* W2   = (const float*)d_in[11];
    const float* b2   = (const float*)d_in[12];
    float* out = (float*)d_out;

    float *xgp, *h0p, *hlastp, *wt0p, *wt1p;
    cudaGetSymbolAddress((void**)&xgp,    g_xg);
    cudaGetSymbolAddress((void**)&h0p,    g_h0);
    cudaGetSymbolAddress((void**)&hlastp, g_hlast);
    cudaGetSymbolAddress((void**)&wt0p,   g_WT0);
    cudaGetSymbolAddress((void**)&wt1p,   g_WT1);

    cudaFuncSetAttribute(lstm_layer_kernel, cudaFuncAttributeMaxDynamicSharedMemorySize, LSTM_SMEM);
    cudaFuncSetAttribute(gemm2_kernel,      cudaFuncAttributeMaxDynamicSharedMemorySize, GEMM_SMEM_MAX);

    prep_whh<<<256, 256>>>(Whh0, wt0p);
    prep_whh<<<256, 256>>>(Whh1, wt1p);

    // layer 0: pre-gates (K=32) then recurrence
    gemm2_kernel<<<dim3(M_TOT / 128, GG / 128), 256, 2 * INDIM * GLD * 4>>>(
        x, Wih0, bih0, bhh0, xgp, M_TOT, GG, INDIM);
    lstm_layer_kernel<<<BB / 4, 512, LSTM_SMEM>>>(xgp, wt0p, h0p, nullptr);

    // layer 1: pre-gates (K=128) then recurrence
    gemm2_kernel<<<dim3(M_TOT / 128, GG / 128), 256, 2 * HH * GLD * 4>>>(
        h0p, Wih1, bih1, bhh1, xgp, M_TOT, GG, HH);
    lstm_layer_kernel<<<BB / 4, 512, LSTM_SMEM>>>(xgp, wt1p, nullptr, hlastp);

    // head + zero hidden_init portion of output
    head_kernel<<<BB, 256>>>(hlastp, W1, b1, W2, b2, out);
    int tail = out_size - BB * OUTD;
    if (tail > 0)
        zero_tail<<<(tail + 255) / 256, 256>>>(out + BB * OUTD, tail);
}

// round 4
// speedup vs baseline: 1.1181x; 1.1181x over previous
#include <cuda_runtime.h>
#include <cstdint>
#include <cstddef>

typedef unsigned long long ull;

#define BB 512
#define TT 1024
#define INDIM 32
#define HH 128
#define GG 512            // 4*H
#define DLL 256
#define OUTD 32
#define M_TOT (BB*TT)     // 524288

// k-pair layout: KP = 64 pairs total; 48 pairs (96 k) in smem, 16 pairs (32 k) in regs (4/quarter)
#define KPSM 48
// smem floats: weights 48*512 *? -> region A 48*128 ull2 + region B 48*128 ull2 = 49152 floats
// + h 512 floats + exchange 4*3*128 float4 = 6144 floats
#define LSTM_SMEM ((49152 + 512 + 6144) * 4)    // 223232 bytes

#define GLD 132

// -------- device scratch (static; no runtime allocation) --------
__device__ float g_xg[(size_t)M_TOT * GG];       // pre-gates for current layer
__device__ float g_h0[(size_t)M_TOT * HH];       // layer-0 hidden sequence
__device__ float g_hlast[BB * HH];
__device__ float g_WT0[HH * GG];                 // Whh0 pair-interleaved (see prep_whh)
__device__ float g_WT1[HH * GG];

// ---------------- f32x2 helpers ----------------
__device__ __forceinline__ ull fma2(ull a, ull b, ull c) {
    ull d;
    asm("fma.rn.f32x2 %0, %1, %2, %3;" : "=l"(d) : "l"(a), "l"(b), "l"(c));
    return d;
}
__device__ __forceinline__ ull add2(ull a, ull b) {
    ull d;
    asm("add.rn.f32x2 %0, %1, %2;" : "=l"(d) : "l"(a), "l"(b));
    return d;
}
__device__ __forceinline__ ull pack2(float x, float y) {
    ull d;
    asm("mov.b64 %0, {%1, %2};" : "=l"(d) : "r"(__float_as_uint(x)), "r"(__float_as_uint(y)));
    return d;
}
__device__ __forceinline__ ull dup2(float x) {
    unsigned v = __float_as_uint(x);
    ull d;
    asm("mov.b64 %0, {%1, %1};" : "=l"(d) : "r"(v));
    return d;
}
__device__ __forceinline__ void unpack2(ull v, float& x, float& y) {
    unsigned a, b;
    asm("mov.b64 {%0, %1}, %2;" : "=r"(a), "=r"(b) : "l"(v));
    x = __uint_as_float(a);
    y = __uint_as_float(b);
}
__device__ __forceinline__ float red2(ull v) {
    float a, b;
    unpack2(v, a, b);
    return a + b;
}

__device__ __forceinline__ float sigf(float x)  { return __fdividef(1.0f, 1.0f + __expf(-x)); }
__device__ __forceinline__ float tanhx(float x) { return __fdividef(2.0f, 1.0f + __expf(-2.0f * x)) - 1.0f; }

// -------- pair-interleave Whh [512][128] into two 16B-granular regions --------
// Region r=0 (gates 0,1), r=1 (gates 2,3); float layout:
//   WTI[r*32768 + kp*512 + j*4 + qq*2 + e] = Whh[((r*2+qq)*128 + j)*128 + 2*kp + e]
__global__ void prep_whh(const float* __restrict__ W, float* __restrict__ WTI) {
    int idx = blockIdx.x * 256 + threadIdx.x;    // 65536 total
    if (idx < HH * GG) {
        int r = idx >> 15;
        int rem = idx & 32767;
        int kp = rem >> 9;
        int rem2 = rem & 511;
        int j = rem2 >> 2;
        int t = rem2 & 3;
        int qq = t >> 1;
        int e = t & 1;
        int q = r * 2 + qq;
        WTI[idx] = W[(q * HH + j) * HH + 2 * kp + e];
    }
}

// -------- 128x128-tile fp32 GEMM (FFMA2), K chunked by 64 for 2 CTAs/SM --------
__global__ void __launch_bounds__(256, 2) gemm2_kernel(
    const float* __restrict__ A, const float* __restrict__ W,
    const float* __restrict__ ba, const float* __restrict__ bb,
    float* __restrict__ C, int M, int N, int K)
{
    extern __shared__ float sm[];
    const int KC = (K < 64) ? K : 64;
    float* sA = sm;                 // [KC][GLD]
    float* sB = sm + KC * GLD;      // [KC][GLD]
    const int tid = threadIdx.x;
    const int m0 = blockIdx.x * 128;
    const int n0 = blockIdx.y * 128;
    const int kv = KC >> 2;

    const int ty = tid >> 4;
    const int tx = tid & 15;
    const int ra = ty * 4;
    const int rb = 64 + ty * 4;
    const int c0 = tx * 4;
    const int c1 = 64 + tx * 4;

    ull acc[8][4];
    #pragma unroll
    for (int i = 0; i < 8; i++)
        #pragma unroll
        for (int p = 0; p < 4; p++) acc[i][p] = 0ULL;

    for (int kc = 0; kc < K; kc += KC) {
        if (kc) __syncthreads();
        for (int idx = tid; idx < 128 * kv; idx += 256) {
            int m = idx / kv;
            int kq = (idx - m * kv) << 2;
            float4 v = *(const float4*)(A + (size_t)(m0 + m) * K + kc + kq);
            sA[(kq + 0) * GLD + m] = v.x;
            sA[(kq + 1) * GLD + m] = v.y;
            sA[(kq + 2) * GLD + m] = v.z;
            sA[(kq + 3) * GLD + m] = v.w;
        }
        for (int idx = tid; idx < 128 * kv; idx += 256) {
            int n = idx / kv;
            int kq = (idx - n * kv) << 2;
            float4 v = *(const float4*)(W + (size_t)(n0 + n) * K + kc + kq);
            sB[(kq + 0) * GLD + n] = v.x;
            sB[(kq + 1) * GLD + n] = v.y;
            sB[(kq + 2) * GLD + n] = v.z;
            sB[(kq + 3) * GLD + n] = v.w;
        }
        __syncthreads();

        #pragma unroll 4
        for (int k = 0; k < KC; k++) {
            float4 a0 = *(const float4*)(sA + k * GLD + ra);
            float4 a1 = *(const float4*)(sA + k * GLD + rb);
            float4 b0 = *(const float4*)(sB + k * GLD + c0);
            float4 b1 = *(const float4*)(sB + k * GLD + c1);
            ull bp0 = pack2(b0.x, b0.y), bp1 = pack2(b0.z, b0.w);
            ull bp2 = pack2(b1.x, b1.y), bp3 = pack2(b1.z, b1.w);
            float av[8] = {a0.x, a0.y, a0.z, a0.w, a1.x, a1.y, a1.z, a1.w};
            #pragma unroll
            for (int i = 0; i < 8; i++) {
                ull d = dup2(av[i]);
                acc[i][0] = fma2(d, bp0, acc[i][0]);
                acc[i][1] = fma2(d, bp1, acc[i][1]);
                acc[i][2] = fma2(d, bp2, acc[i][2]);
                acc[i][3] = fma2(d, bp3, acc[i][3]);
            }
        }
    }

    ull bias0 = pack2(ba[n0 + c0 + 0] + bb[n0 + c0 + 0], ba[n0 + c0 + 1] + bb[n0 + c0 + 1]);
    ull bias1 = pack2(ba[n0 + c0 + 2] + bb[n0 + c0 + 2], ba[n0 + c0 + 3] + bb[n0 + c0 + 3]);
    ull bias2 = pack2(ba[n0 + c1 + 0] + bb[n0 + c1 + 0], ba[n0 + c1 + 1] + bb[n0 + c1 + 1]);
    ull bias3 = pack2(ba[n0 + c1 + 2] + bb[n0 + c1 + 2], ba[n0 + c1 + 3] + bb[n0 + c1 + 3]);

    #pragma unroll
    for (int i = 0; i < 8; i++) {
        int row = m0 + (i < 4 ? ra + i : rb + i - 4);
        ull* p0 = (ull*)(C + (size_t)row * N + n0 + c0);
        p0[0] = add2(acc[i][0], bias0);
        p0[1] = add2(acc[i][1], bias1);
        ull* p1 = (ull*)(C + (size_t)row * N + n0 + c1);
        p1[0] = add2(acc[i][2], bias2);
        p1[1] = add2(acc[i][3], bias3);
    }
}

// -------- LSTM recurrence: 4 rows/CTA, 512 threads, 4-way k split, k-pair FFMA2 --------
// acc[r][q] is an f32x2 pair (even-k partial, odd-k partial); no dup movs anywhere.

#define MAC4(HV0, HV1, HV2, HV3, W0, W1) { \
    a00 = fma2(HV0, W0.x, a00); a01 = fma2(HV0, W0.y, a01); \
    a02 = fma2(HV0, W1.x, a02); a03 = fma2(HV0, W1.y, a03); \
    a10 = fma2(HV1, W0.x, a10); a11 = fma2(HV1, W0.y, a11); \
    a12 = fma2(HV1, W1.x, a12); a13 = fma2(HV1, W1.y, a13); \
    a20 = fma2(HV2, W0.x, a20); a21 = fma2(HV2, W0.y, a21); \
    a22 = fma2(HV2, W1.x, a22); a23 = fma2(HV2, W1.y, a23); \
    a30 = fma2(HV3, W0.x, a30); a31 = fma2(HV3, W0.y, a31); \
    a32 = fma2(HV3, W1.x, a32); a33 = fma2(HV3, W1.y, a33); }

__global__ void __launch_bounds__(512, 1) lstm_layer_kernel(
    const float* __restrict__ xg,      // [M_TOT][512] pre-gates, row = b*T + t
    const float* __restrict__ WTI,     // pair-interleaved Whh (see prep_whh)
    float* __restrict__ hout,          // [M_TOT][128] or nullptr
    float* __restrict__ hlast)         // [B][128]     or nullptr
{
    extern __shared__ float sm[];
    // smem: [0,24576) region A weights (kp 0..47), [24576,49152) region B,
    //       [49152,49664) h[4][128], [49664, +6144) exchange float4[4][3][128]
    const ulonglong2* swA = (const ulonglong2*)sm;          // 6144 ull2
    const ulonglong2* swB = swA + 6144;
    float* sh = sm + 49152;
    float4* sxf = (float4*)(sm + 49152 + 512);

    const int tid = threadIdx.x;
    const int j = tid & 127;
    const int u = tid >> 7;              // quarter 0..3
    const int b0 = blockIdx.x * 4;

    // load weight regions for kp in [0,48) into smem
    {
        const float4* g4 = (const float4*)WTI;
        float4* s4 = (float4*)sm;
        #pragma unroll 4
        for (int i = tid; i < 6144; i += 512) s4[i] = g4[i];          // region A
        #pragma unroll 4
        for (int i = tid; i < 6144; i += 512) s4[6144 + i] = g4[8192 + i];  // region B
    }
    // tail kp in [48 + u*4, 48 + u*4 + 4) in registers
    ulonglong2 wtA[4], wtB[4];
    {
        const ulonglong2* gA = (const ulonglong2*)WTI;
        const ulonglong2* gB = gA + 8192;
        int kt = KPSM + u * 4;
        #pragma unroll
        for (int i = 0; i < 4; i++) {
            wtA[i] = gA[(size_t)(kt + i) * 128 + j];
            wtB[i] = gB[(size_t)(kt + i) * 128 + j];
        }
    }
    sh[tid] = 0.0f;

    const int klo = u * 24;             // float-k offset of this quarter's smem range
    const int kplo = u * 12;            // kp offset

    const size_t xbase = ((size_t)(b0 + u)) * TT * GG + j;
    float* houtP = hout ? hout + ((size_t)(b0 + u)) * TT * HH + j : (float*)0;

    float xc0 = xg[xbase], xc1 = xg[xbase + 128], xc2 = xg[xbase + 256], xc3 = xg[xbase + 384];

    float cc = 0.0f, hh = 0.0f;
    __syncthreads();

    for (int t = 0; t < TT; t++) {
        ull a00 = 0, a01 = 0, a02 = 0, a03 = 0;
        ull a10 = 0, a11 = 0, a12 = 0, a13 = 0;
        ull a20 = 0, a21 = 0, a22 = 0, a23 = 0;
        ull a30 = 0, a31 = 0, a32 = 0, a33 = 0;

        // prefetch next step's own-row pre-gates
        float xn0 = 0, xn1 = 0, xn2 = 0, xn3 = 0;
        if (t + 1 < TT) {
            size_t o = xbase + (size_t)(t + 1) * GG;
            xn0 = xg[o]; xn1 = xg[o + 128]; xn2 = xg[o + 256]; xn3 = xg[o + 384];
        }

        // smem kp range: 12 kp (6 groups of 2 kp = 4 k)
        #pragma unroll
        for (int g = 0; g < 6; g++) {
            int kb = klo + g * 4;
            ulonglong2 H0 = *(const ulonglong2*)(sh + kb);
            ulonglong2 H1 = *(const ulonglong2*)(sh + 128 + kb);
            ulonglong2 H2 = *(const ulonglong2*)(sh + 256 + kb);
            ulonglong2 H3 = *(const ulonglong2*)(sh + 384 + kb);
            int kpi = (kplo + g * 2) * 128 + j;
            ulonglong2 w0 = swA[kpi];
            ulonglong2 w1 = swB[kpi];
            MAC4(H0.x, H1.x, H2.x, H3.x, w0, w1);
            ulonglong2 w2 = swA[kpi + 128];
            ulonglong2 w3 = swB[kpi + 128];
            MAC4(H0.y, H1.y, H2.y, H3.y, w2, w3);
        }
        // register tail: 4 kp (2 groups)
        #pragma unroll
        for (int g = 0; g < 2; g++) {
            int kb = 96 + u * 8 + g * 4;
            ulonglong2 H0 = *(const ulonglong2*)(sh + kb);
            ulonglong2 H1 = *(const ulonglong2*)(sh + 128 + kb);
            ulonglong2 H2 = *(const ulonglong2*)(sh + 256 + kb);
            ulonglong2 H3 = *(const ulonglong2*)(sh + 384 + kb);
            MAC4(H0.x, H1.x, H2.x, H3.x, wtA[g * 2], wtB[g * 2]);
            MAC4(H0.y, H1.y, H2.y, H3.y, wtA[g * 2 + 1], wtB[g * 2 + 1]);
        }

        // reduce pair lanes -> per-row float4 gate partials
        float4 s0, s1, s2, s3;
        s0.x = red2(a00); s0.y = red2(a01); s0.z = red2(a02); s0.w = red2(a03);
        s1.x = red2(a10); s1.y = red2(a11); s1.z = red2(a12); s1.w = red2(a13);
        s2.x = red2(a20); s2.y = red2(a21); s2.z = red2(a22); s2.w = red2(a23);
        s3.x = red2(a30); s3.y = red2(a31); s3.z = red2(a32); s3.w = red2(a33);

        // exchange foreign partials; slot = u - (u > r)
        if (u != 0) sxf[(0 * 3 + (u - 1)) * 128 + j] = s0;
        if (u != 1) sxf[(1 * 3 + ((u == 0) ? 0 : u - 1)) * 128 + j] = s1;
        if (u != 2) sxf[(2 * 3 + ((u == 3) ? 2 : u)) * 128 + j] = s2;
        if (u != 3) sxf[(3 * 3 + u) * 128 + j] = s3;
        __syncthreads();
        {
            float4 own = (u == 0) ? s0 : (u == 1) ? s1 : (u == 2) ? s2 : s3;
            float4 p0 = sxf[u * 384 + j];
            float4 p1 = sxf[u * 384 + 128 + j];
            float4 p2 = sxf[u * 384 + 256 + j];
            float gi = own.x + xc0 + p0.x + p1.x + p2.x;
            float gf = own.y + xc1 + p0.y + p1.y + p2.y;
            float gg2 = own.z + xc2 + p0.z + p1.z + p2.z;
            float go = own.w + xc3 + p0.w + p1.w + p2.w;

            float ii = sigf(gi), ff = sigf(gf), g = tanhx(gg2), oo = sigf(go);
            cc = ff * cc + ii * g;
            hh = oo * tanhx(cc);

            sh[u * 128 + j] = hh;
            if (hout) houtP[(size_t)t * HH] = hh;
        }
        xc0 = xn0; xc1 = xn1; xc2 = xn2; xc3 = xn3;
        __syncthreads();
    }

    if (hlast) hlast[(b0 + u) * HH + j] = hh;
}

// -------- MLP head: y = celu(celu(last @ W1^T + b1) @ W2^T + b2) --------
__device__ __forceinline__ float celuf(float x) { return x > 0.0f ? x : expm1f(x); }

__global__ void __launch_bounds__(256) head_kernel(
    const float* __restrict__ hlast,
    const float* __restrict__ W1, const float* __restrict__ b1,
    const float* __restrict__ W2, const float* __restrict__ b2,
    float* __restrict__ out)
{
    const int b = blockIdx.x;
    const int tid = threadIdx.x;
    __shared__ float sl[HH];
    __shared__ float sy[DLL];

    if (tid < HH) sl[tid] = hlast[b * HH + tid];
    __syncthreads();

    float s = b1[tid];
    const float* w = W1 + (size_t)tid * HH;
    #pragma unroll 8
    for (int k = 0; k < HH; k++) s += sl[k] * w[k];
    sy[tid] = celuf(s);
    __syncthreads();

    if (tid < OUTD) {
        float s2 = b2[tid];
        const float* w2 = W2 + (size_t)tid * DLL;
        #pragma unroll 8
        for (int k = 0; k < DLL; k++) s2 += sy[k] * w2[k];
        out[b * OUTD + tid] = celuf(s2);
    }
}

__global__ void zero_tail(float* __restrict__ p, int n) {
    int i = blockIdx.x * 256 + threadIdx.x;
    if (i < n) p[i] = 0.0f;
}

// -------- launch --------
extern "C" void kernel_launch(void* const* d_in, const int* in_sizes, int n_in,
                              void* d_out, int out_size)
{
    const float* x    = (const float*)d_in[0];
    const float* Wih0 = (const float*)d_in[1];
    const float* Whh0 = (const float*)d_in[2];
    const float* bih0 = (const float*)d_in[3];
    const float* bhh0 = (const float*)d_in[4];
    const float* Wih1 = (const float*)d_in[5];
    const float* Whh1 = (const float*)d_in[6];
    const float* bih1 = (const float*)d_in[7];
    const float* bhh1 = (const float*)d_in[8];
    const float* W1   = (const float*)d_in[9];
    const float* b1   = (const float*)d_in[10];
    const float* W2   = (const float*)d_in[11];
    const float* b2   = (const float*)d_in[12];
    float* out = (float*)d_out;

    float *xgp, *h0p, *hlastp, *wt0p, *wt1p;
    cudaGetSymbolAddress((void**)&xgp,    g_xg);
    cudaGetSymbolAddress((void**)&h0p,    g_h0);
    cudaGetSymbolAddress((void**)&hlastp, g_hlast);
    cudaGetSymbolAddress((void**)&wt0p,   g_WT0);
    cudaGetSymbolAddress((void**)&wt1p,   g_WT1);

    cudaFuncSetAttribute(lstm_layer_kernel, cudaFuncAttributeMaxDynamicSharedMemorySize, LSTM_SMEM);
    cudaFuncSetAttribute(gemm2_kernel,      cudaFuncAttributeMaxDynamicSharedMemorySize, 2 * 64 * GLD * 4);

    prep_whh<<<256, 256>>>(Whh0, wt0p);
    prep_whh<<<256, 256>>>(Whh1, wt1p);

    // layer 0: pre-gates (K=32) then recurrence
    gemm2_kernel<<<dim3(M_TOT / 128, GG / 128), 256, 2 * INDIM * GLD * 4>>>(
        x, Wih0, bih0, bhh0, xgp, M_TOT, GG, INDIM);
    lstm_layer_kernel<<<BB / 4, 512, LSTM_SMEM>>>(xgp, wt0p, h0p, nullptr);

    // layer 1: pre-gates (K=128, two 64-k chunks) then recurrence
    gemm2_kernel<<<dim3(M_TOT / 128, GG / 128), 256, 2 * 64 * GLD * 4>>>(
        h0p, Wih1, bih1, bhh1, xgp, M_TOT, GG, HH);
    lstm_layer_kernel<<<BB / 4, 512, LSTM_SMEM>>>(xgp, wt1p, nullptr, hlastp);

    // head + zero hidden_init portion of output
    head_kernel<<<BB, 256>>>(hlastp, W1, b1, W2, b2, out);
    int tail = out_size - BB * OUTD;
    if (tail > 0)
        zero_tail<<<(tail + 255) / 256, 256>>>(out + BB * OUTD, tail);
}

// round 6
// speedup vs baseline: 1.2792x; 1.1440x over previous
#include <cuda_runtime.h>
#include <cuda_bf16.h>
#include <cstdint>
#include <cstddef>

typedef unsigned long long ull;

#define BB 512
#define TT 1024
#define INDIM 32
#define HH 128
#define GG 512            // 4*H
#define DLL 256
#define OUTD 32
#define M_TOT (BB*TT)     // 524288

// ---- lstm smem layout (round-4, proven) ----
#define KPSM 48
#define LSTM_SMEM ((49152 + 512 + 6144) * 4)    // 223232 bytes

// -------- device scratch (static; no runtime allocation) --------
__device__ float g_xg[(size_t)M_TOT * GG];
__device__ float g_h0[(size_t)M_TOT * HH];
__device__ float g_hlast[BB * HH];
__device__ float g_WT0[HH * GG];
__device__ float g_WT1[HH * GG];

// ---------------- f32x2 helpers (lstm) ----------------
__device__ __forceinline__ ull fma2(ull a, ull b, ull c) {
    ull d;
    asm("fma.rn.f32x2 %0, %1, %2, %3;" : "=l"(d) : "l"(a), "l"(b), "l"(c));
    return d;
}
__device__ __forceinline__ void unpack2(ull v, float& x, float& y) {
    unsigned a, b;
    asm("mov.b64 {%0, %1}, %2;" : "=r"(a), "=r"(b) : "l"(v));
    x = __uint_as_float(a);
    y = __uint_as_float(b);
}
__device__ __forceinline__ float red2(ull v) {
    float a, b;
    unpack2(v, a, b);
    return a + b;
}
__device__ __forceinline__ float sigf(float x)  { return __fdividef(1.0f, 1.0f + __expf(-x)); }
__device__ __forceinline__ float tanhx(float x) { return __fdividef(2.0f, 1.0f + __expf(-2.0f * x)) - 1.0f; }

// -------- interleave Whh for lstm (unchanged) --------
__global__ void prep_whh(const float* __restrict__ W, float* __restrict__ WTI) {
    int idx = blockIdx.x * 256 + threadIdx.x;
    if (idx < HH * GG) {
        int r = idx >> 15;
        int rem = idx & 32767;
        int kp = rem >> 9;
        int rem2 = rem & 511;
        int j = rem2 >> 2;
        int t = rem2 & 3;
        int qq = t >> 1;
        int e = t & 1;
        int q = r * 2 + qq;
        WTI[idx] = W[(q * HH + j) * HH + 2 * kp + e];
    }
}

// ================= mma.sync bf16 hi/lo pre-gate GEMM =================
// C[m][n] = sum_k A[m][k]*W[n][k] + ba[n] + bb[n]
// CTA tile: 128m x 128n, K chunked by 32. 8 warps, warp tile 32m x 64n.
// 3-MMA split: Ahi*Whi + Alo*Whi + Ahi*Wlo (fp32 accumulate).

#define MMA_BF16(D, A0, A1, A2, A3, B0, B1) \
    asm volatile( \
        "mma.sync.aligned.m16n8k16.row.col.f32.bf16.bf16.f32 " \
        "{%0,%1,%2,%3}, {%4,%5,%6,%7}, {%8,%9}, {%0,%1,%2,%3};" \
        : "+f"((D)[0]), "+f"((D)[1]), "+f"((D)[2]), "+f"((D)[3]) \
        : "r"(A0), "r"(A1), "r"(A2), "r"(A3), "r"(B0), "r"(B1))

__global__ void __launch_bounds__(256) mma_pregate(
    const float* __restrict__ A,     // [M][K] fp32
    const float* __restrict__ W,     // [512][K] fp32
    const float* __restrict__ ba, const float* __restrict__ bb,
    float* __restrict__ C,           // [M][512]
    int K)
{
    // padded bf16 tiles: row stride 40 elements (80 B) -> conflict-free frag loads
    __shared__ __nv_bfloat16 sAhi[128][40];
    __shared__ __nv_bfloat16 sAlo[128][40];
    __shared__ __nv_bfloat16 sWhi[128][40];
    __shared__ __nv_bfloat16 sWlo[128][40];
    __shared__ float sbias[128];

    const int tid = threadIdx.x;
    const int lane = tid & 31;
    const int wid = tid >> 5;
    const int wm = wid & 3;              // warp m index: rows wm*32 .. +32
    const int wn = wid >> 2;             // warp n index: cols wn*64 .. +64
    const int g = lane >> 2;             // group id 0..7
    const int tig = lane & 3;            // thread-in-group

    const int m0 = blockIdx.x * 128;
    const int n0 = blockIdx.y * 128;

    if (tid < 128) sbias[tid] = ba[n0 + tid] + bb[n0 + tid];

    float d[2][8][4];
    #pragma unroll
    for (int mf = 0; mf < 2; mf++)
        #pragma unroll
        for (int nf = 0; nf < 8; nf++)
            #pragma unroll
            for (int e = 0; e < 4; e++) d[mf][nf][e] = 0.0f;

    for (int kc = 0; kc < K; kc += 32) {
        if (kc) __syncthreads();
        // load + convert A and W chunks (128 rows x 32 k each)
        #pragma unroll
        for (int idx = tid; idx < 1024; idx += 256) {
            int row = idx >> 3;
            int q = idx & 7;
            float4 v = *(const float4*)(A + (size_t)(m0 + row) * K + kc + q * 4);
            __nv_bfloat162 h01 = __floats2bfloat162_rn(v.x, v.y);
            __nv_bfloat162 h23 = __floats2bfloat162_rn(v.z, v.w);
            __nv_bfloat162 l01 = __floats2bfloat162_rn(v.x - __bfloat162float(h01.x),
                                                       v.y - __bfloat162float(h01.y));
            __nv_bfloat162 l23 = __floats2bfloat162_rn(v.z - __bfloat162float(h23.x),
                                                       v.w - __bfloat162float(h23.y));
            uint2 oh, ol;
            oh.x = *(uint32_t*)&h01; oh.y = *(uint32_t*)&h23;
            ol.x = *(uint32_t*)&l01; ol.y = *(uint32_t*)&l23;
            *(uint2*)(&sAhi[row][q * 4]) = oh;
            *(uint2*)(&sAlo[row][q * 4]) = ol;
        }
        #pragma unroll
        for (int idx = tid; idx < 1024; idx += 256) {
            int row = idx >> 3;
            int q = idx & 7;
            float4 v = *(const float4*)(W + (size_t)(n0 + row) * K + kc + q * 4);
            __nv_bfloat162 h01 = __floats2bfloat162_rn(v.x, v.y);
            __nv_bfloat162 h23 = __floats2bfloat162_rn(v.z, v.w);
            __nv_bfloat162 l01 = __floats2bfloat162_rn(v.x - __bfloat162float(h01.x),
                                                       v.y - __bfloat162float(h01.y));
            __nv_bfloat162 l23 = __floats2bfloat162_rn(v.z - __bfloat162float(h23.x),
                                                       v.w - __bfloat162float(h23.y));
            uint2 oh, ol;
            oh.x = *(uint32_t*)&h01; oh.y = *(uint32_t*)&h23;
            ol.x = *(uint32_t*)&l01; ol.y = *(uint32_t*)&l23;
            *(uint2*)(&sWhi[row][q * 4]) = oh;
            *(uint2*)(&sWlo[row][q * 4]) = ol;
        }
        __syncthreads();

        #pragma unroll
        for (int ks = 0; ks < 2; ks++) {
            const int c0 = ks * 16 + 2 * tig;
            const int c1 = c0 + 8;

            uint32_t AH[2][4], AL[2][4];
            #pragma unroll
            for (int mf = 0; mf < 2; mf++) {
                int r0 = wm * 32 + mf * 16 + g;
                AH[mf][0] = *(const uint32_t*)(&sAhi[r0][c0]);
                AH[mf][1] = *(const uint32_t*)(&sAhi[r0 + 8][c0]);
                AH[mf][2] = *(const uint32_t*)(&sAhi[r0][c1]);
                AH[mf][3] = *(const uint32_t*)(&sAhi[r0 + 8][c1]);
                AL[mf][0] = *(const uint32_t*)(&sAlo[r0][c0]);
                AL[mf][1] = *(const uint32_t*)(&sAlo[r0 + 8][c0]);
                AL[mf][2] = *(const uint32_t*)(&sAlo[r0][c1]);
                AL[mf][3] = *(const uint32_t*)(&sAlo[r0 + 8][c1]);
            }
            #pragma unroll
            for (int nf = 0; nf < 8; nf++) {
                int rb = wn * 64 + nf * 8 + g;
                uint32_t BH0 = *(const uint32_t*)(&sWhi[rb][c0]);
                uint32_t BH1 = *(const uint32_t*)(&sWhi[rb][c1]);
                uint32_t BL0 = *(const uint32_t*)(&sWlo[rb][c0]);
                uint32_t BL1 = *(const uint32_t*)(&sWlo[rb][c1]);
                #pragma unroll
                for (int mf = 0; mf < 2; mf++) {
                    MMA_BF16(d[mf][nf], AH[mf][0], AH[mf][1], AH[mf][2], AH[mf][3], BH0, BH1);
                    MMA_BF16(d[mf][nf], AL[mf][0], AL[mf][1], AL[mf][2], AL[mf][3], BH0, BH1);
                    MMA_BF16(d[mf][nf], AH[mf][0], AH[mf][1], AH[mf][2], AH[mf][3], BL0, BL1);
                }
            }
        }
    }

    // epilogue: add bias, store float2 pairs
    #pragma unroll
    for (int mf = 0; mf < 2; mf++) {
        int r0 = wm * 32 + mf * 16 + g;
        #pragma unroll
        for (int nf = 0; nf < 8; nf++) {
            int nl = wn * 64 + nf * 8 + 2 * tig;
            float bx = sbias[nl];
            float by = sbias[nl + 1];
            float2 o0, o1;
            o0.x = d[mf][nf][0] + bx; o0.y = d[mf][nf][1] + by;
            o1.x = d[mf][nf][2] + bx; o1.y = d[mf][nf][3] + by;
            *(float2*)(C + (size_t)(m0 + r0) * GG + n0 + nl) = o0;
            *(float2*)(C + (size_t)(m0 + r0 + 8) * GG + n0 + nl) = o1;
        }
    }
}

// -------- LSTM recurrence (round-4, unchanged) --------
#define MAC4(HV0, HV1, HV2, HV3, W0, W1) { \
    a00 = fma2(HV0, W0.x, a00); a01 = fma2(HV0, W0.y, a01); \
    a02 = fma2(HV0, W1.x, a02); a03 = fma2(HV0, W1.y, a03); \
    a10 = fma2(HV1, W0.x, a10); a11 = fma2(HV1, W0.y, a11); \
    a12 = fma2(HV1, W1.x, a12); a13 = fma2(HV1, W1.y, a13); \
    a20 = fma2(HV2, W0.x, a20); a21 = fma2(HV2, W0.y, a21); \
    a22 = fma2(HV2, W1.x, a22); a23 = fma2(HV2, W1.y, a23); \
    a30 = fma2(HV3, W0.x, a30); a31 = fma2(HV3, W0.y, a31); \
    a32 = fma2(HV3, W1.x, a32); a33 = fma2(HV3, W1.y, a33); }

__global__ void __launch_bounds__(512, 1) lstm_layer_kernel(
    const float* __restrict__ xg,
    const float* __restrict__ WTI,
    float* __restrict__ hout,
    float* __restrict__ hlast)
{
    extern __shared__ float sm[];
    const ulonglong2* swA = (const ulonglong2*)sm;
    const ulonglong2* swB = swA + 6144;
    float* sh = sm + 49152;
    float4* sxf = (float4*)(sm + 49152 + 512);

    const int tid = threadIdx.x;
    const int j = tid & 127;
    const int u = tid >> 7;
    const int b0 = blockIdx.x * 4;

    {
        const float4* g4 = (const float4*)WTI;
        float4* s4 = (float4*)sm;
        #pragma unroll 4
        for (int i = tid; i < 6144; i += 512) s4[i] = g4[i];
        #pragma unroll 4
        for (int i = tid; i < 6144; i += 512) s4[6144 + i] = g4[8192 + i];
    }
    ulonglong2 wtA[4], wtB[4];
    {
        const ulonglong2* gA = (const ulonglong2*)WTI;
        const ulonglong2* gB = gA + 8192;
        int kt = KPSM + u * 4;
        #pragma unroll
        for (int i = 0; i < 4; i++) {
            wtA[i] = gA[(size_t)(kt + i) * 128 + j];
            wtB[i] = gB[(size_t)(kt + i) * 128 + j];
        }
    }
    sh[tid] = 0.0f;

    const int klo = u * 24;
    const int kplo = u * 12;

    const size_t xbase = ((size_t)(b0 + u)) * TT * GG + j;
    float* houtP = hout ? hout + ((size_t)(b0 + u)) * TT * HH + j : (float*)0;

    float xc0 = xg[xbase], xc1 = xg[xbase + 128], xc2 = xg[xbase + 256], xc3 = xg[xbase + 384];

    float cc = 0.0f, hh = 0.0f;
    __syncthreads();

    for (int t = 0; t < TT; t++) {
        ull a00 = 0, a01 = 0, a02 = 0, a03 = 0;
        ull a10 = 0, a11 = 0, a12 = 0, a13 = 0;
        ull a20 = 0, a21 = 0, a22 = 0, a23 = 0;
        ull a30 = 0, a31 = 0, a32 = 0, a33 = 0;

        float xn0 = 0, xn1 = 0, xn2 = 0, xn3 = 0;
        if (t + 1 < TT) {
            size_t o = xbase + (size_t)(t + 1) * GG;
            xn0 = xg[o]; xn1 = xg[o + 128]; xn2 = xg[o + 256]; xn3 = xg[o + 384];
        }

        #pragma unroll
        for (int g = 0; g < 6; g++) {
            int kb = klo + g * 4;
            ulonglong2 H0 = *(const ulonglong2*)(sh + kb);
            ulonglong2 H1 = *(const ulonglong2*)(sh + 128 + kb);
            ulonglong2 H2 = *(const ulonglong2*)(sh + 256 + kb);
            ulonglong2 H3 = *(const ulonglong2*)(sh + 384 + kb);
            int kpi = (kplo + g * 2) * 128 + j;
            ulonglong2 w0 = swA[kpi];
            ulonglong2 w1 = swB[kpi];
            MAC4(H0.x, H1.x, H2.x, H3.x, w0, w1);
            ulonglong2 w2 = swA[kpi + 128];
            ulonglong2 w3 = swB[kpi + 128];
            MAC4(H0.y, H1.y, H2.y, H3.y, w2, w3);
        }
        #pragma unroll
        for (int g = 0; g < 2; g++) {
            int kb = 96 + u * 8 + g * 4;
            ulonglong2 H0 = *(const ulonglong2*)(sh + kb);
            ulonglong2 H1 = *(const ulonglong2*)(sh + 128 + kb);
            ulonglong2 H2 = *(const ulonglong2*)(sh + 256 + kb);
            ulonglong2 H3 = *(const ulonglong2*)(sh + 384 + kb);
            MAC4(H0.x, H1.x, H2.x, H3.x, wtA[g * 2], wtB[g * 2]);
            MAC4(H0.y, H1.y, H2.y, H3.y, wtA[g * 2 + 1], wtB[g * 2 + 1]);
        }

        float4 s0, s1, s2, s3;
        s0.x = red2(a00); s0.y = red2(a01); s0.z = red2(a02); s0.w = red2(a03);
        s1.x = red2(a10); s1.y = red2(a11); s1.z = red2(a12); s1.w = red2(a13);
        s2.x = red2(a20); s2.y = red2(a21); s2.z = red2(a22); s2.w = red2(a23);
        s3.x = red2(a30); s3.y = red2(a31); s3.z = red2(a32); s3.w = red2(a33);

        if (u != 0) sxf[(0 * 3 + (u - 1)) * 128 + j] = s0;
        if (u != 1) sxf[(1 * 3 + ((u == 0) ? 0 : u - 1)) * 128 + j] = s1;
        if (u != 2) sxf[(2 * 3 + ((u == 3) ? 2 : u)) * 128 + j] = s2;
        if (u != 3) sxf[(3 * 3 + u) * 128 + j] = s3;
        __syncthreads();
        {
            float4 own = (u == 0) ? s0 : (u == 1) ? s1 : (u == 2) ? s2 : s3;
            float4 p0 = sxf[u * 384 + j];
            float4 p1 = sxf[u * 384 + 128 + j];
            float4 p2 = sxf[u * 384 + 256 + j];
            float gi = own.x + xc0 + p0.x + p1.x + p2.x;
            float gf = own.y + xc1 + p0.y + p1.y + p2.y;
            float gg2 = own.z + xc2 + p0.z + p1.z + p2.z;
            float go = own.w + xc3 + p0.w + p1.w + p2.w;

            float ii = sigf(gi), ff = sigf(gf), g = tanhx(gg2), oo = sigf(go);
            cc = ff * cc + ii * g;
            hh = oo * tanhx(cc);

            sh[u * 128 + j] = hh;
            if (hout) houtP[(size_t)t * HH] = hh;
        }
        xc0 = xn0; xc1 = xn1; xc2 = xn2; xc3 = xn3;
        __syncthreads();
    }

    if (hlast) hlast[(b0 + u) * HH + j] = hh;
}

// -------- MLP head --------
__device__ __forceinline__ float celuf(float x) { return x > 0.0f ? x : expm1f(x); }

__global__ void __launch_bounds__(256) head_kernel(
    const float* __restrict__ hlast,
    const float* __restrict__ W1, const float* __restrict__ b1,
    const float* __restrict__ W2, const float* __restrict__ b2,
    float* __restrict__ out)
{
    const int b = blockIdx.x;
    const int tid = threadIdx.x;
    __shared__ float sl[HH];
    __shared__ float sy[DLL];

    if (tid < HH) sl[tid] = hlast[b * HH + tid];
    __syncthreads();

    float s = b1[tid];
    const float* w = W1 + (size_t)tid * HH;
    #pragma unroll 8
    for (int k = 0; k < HH; k++) s += sl[k] * w[k];
    sy[tid] = celuf(s);
    __syncthreads();

    if (tid < OUTD) {
        float s2 = b2[tid];
        const float* w2 = W2 + (size_t)tid * DLL;
        #pragma unroll 8
        for (int k = 0; k < DLL; k++) s2 += sy[k] * w2[k];
        out[b * OUTD + tid] = celuf(s2);
    }
}

__global__ void zero_tail(float* __restrict__ p, int n) {
    int i = blockIdx.x * 256 + threadIdx.x;
    if (i < n) p[i] = 0.0f;
}

// -------- launch --------
extern "C" void kernel_launch(void* const* d_in, const int* in_sizes, int n_in,
                              void* d_out, int out_size)
{
    const float* x    = (const float*)d_in[0];
    const float* Wih0 = (const float*)d_in[1];
    const float* Whh0 = (const float*)d_in[2];
    const float* bih0 = (const float*)d_in[3];
    const float* bhh0 = (const float*)d_in[4];
    const float* Wih1 = (const float*)d_in[5];
    const float* Whh1 = (const float*)d_in[6];
    const float* bih1 = (const float*)d_in[7];
    const float* bhh1 = (const float*)d_in[8];
    const float* W1   = (const float*)d_in[9];
    const float* b1   = (const float*)d_in[10];
    const float* W2   = (const float*)d_in[11];
    const float* b2   = (const float*)d_in[12];
    float* out = (float*)d_out;

    float *xgp, *h0p, *hlastp, *wt0p, *wt1p;
    cudaGetSymbolAddress((void**)&xgp,    g_xg);
    cudaGetSymbolAddress((void**)&h0p,    g_h0);
    cudaGetSymbolAddress((void**)&hlastp, g_hlast);
    cudaGetSymbolAddress((void**)&wt0p,   g_WT0);
    cudaGetSymbolAddress((void**)&wt1p,   g_WT1);

    cudaFuncSetAttribute(lstm_layer_kernel, cudaFuncAttributeMaxDynamicSharedMemorySize, LSTM_SMEM);

    prep_whh<<<256, 256>>>(Whh0, wt0p);
    prep_whh<<<256, 256>>>(Whh1, wt1p);

    // layer 0: pre-gates (mma.sync bf16 split, K=32) then recurrence
    mma_pregate<<<dim3(M_TOT / 128, GG / 128), 256>>>(x, Wih0, bih0, bhh0, xgp, INDIM);
    lstm_layer_kernel<<<BB / 4, 512, LSTM_SMEM>>>(xgp, wt0p, h0p, nullptr);

    // layer 1: pre-gates (mma.sync bf16 split, K=128) then recurrence
    mma_pregate<<<dim3(M_TOT / 128, GG / 128), 256>>>(h0p, Wih1, bih1, bhh1, xgp, HH);
    lstm_layer_kernel<<<BB / 4, 512, LSTM_SMEM>>>(xgp, wt1p, nullptr, hlastp);

    head_kernel<<<BB, 256>>>(hlastp, W1, b1, W2, b2, out);
    int tail = out_size - BB * OUTD;
    if (tail > 0)
        zero_tail<<<(tail + 255) / 256, 256>>>(out + BB * OUTD, tail);
}

// round 7
// speedup vs baseline: 1.3457x; 1.0520x over previous
#include <cuda_runtime.h>
#include <cuda_bf16.h>
#include <cstdint>
#include <cstddef>

typedef unsigned long long ull;

#define BB 512
#define TT 1024
#define INDIM 32
#define HH 128
#define GG 512            // 4*H
#define DLL 256
#define OUTD 32
#define M_TOT (BB*TT)     // 524288

// ---- lstm smem layout (round-4, proven) ----
#define KPSM 48
#define LSTM_SMEM ((49152 + 512 + 6144) * 4)    // 223232 bytes

// -------- device scratch (static; no runtime allocation) --------
__device__ float g_xg[(size_t)M_TOT * GG];
__device__ float g_h0[(size_t)M_TOT * HH];
__device__ float g_hlast[BB * HH];
__device__ float g_WT0[HH * GG];
__device__ float g_WT1[HH * GG];

// ---------------- f32x2 helpers (lstm) ----------------
__device__ __forceinline__ ull fma2(ull a, ull b, ull c) {
    ull d;
    asm("fma.rn.f32x2 %0, %1, %2, %3;" : "=l"(d) : "l"(a), "l"(b), "l"(c));
    return d;
}
__device__ __forceinline__ void unpack2(ull v, float& x, float& y) {
    unsigned a, b;
    asm("mov.b64 {%0, %1}, %2;" : "=r"(a), "=r"(b) : "l"(v));
    x = __uint_as_float(a);
    y = __uint_as_float(b);
}
__device__ __forceinline__ float red2(ull v) {
    float a, b;
    unpack2(v, a, b);
    return a + b;
}
__device__ __forceinline__ float sigf(float x)  { return __fdividef(1.0f, 1.0f + __expf(-x)); }
__device__ __forceinline__ float tanhx(float x) { return __fdividef(2.0f, 1.0f + __expf(-2.0f * x)) - 1.0f; }

// -------- interleave Whh for lstm (unchanged) --------
__global__ void prep_whh(const float* __restrict__ W, float* __restrict__ WTI) {
    int idx = blockIdx.x * 256 + threadIdx.x;
    if (idx < HH * GG) {
        int r = idx >> 15;
        int rem = idx & 32767;
        int kp = rem >> 9;
        int rem2 = rem & 511;
        int j = rem2 >> 2;
        int t = rem2 & 3;
        int qq = t >> 1;
        int e = t & 1;
        int q = r * 2 + qq;
        WTI[idx] = W[(q * HH + j) * HH + 2 * kp + e];
    }
}

// ================= mma.sync bf16 hi/lo pre-gate GEMM =================
// C[m][n] = sum_k A[m][k]*W[n][k] + ba[n] + bb[n]
// grid (M/128): each CTA converts its 128xK A tile ONCE, then loops the 4
// n-blocks of 128, converting the (L2-resident) W block per iteration.
// 8 warps, warp tile 32m x 64n. 3-MMA split: Ahi*Whi + Alo*Whi + Ahi*Wlo.

#define MMA_BF16(D, A0, A1, A2, A3, B0, B1) \
    asm volatile( \
        "mma.sync.aligned.m16n8k16.row.col.f32.bf16.bf16.f32 " \
        "{%0,%1,%2,%3}, {%4,%5,%6,%7}, {%8,%9}, {%0,%1,%2,%3};" \
        : "+f"((D)[0]), "+f"((D)[1]), "+f"((D)[2]), "+f"((D)[3]) \
        : "r"(A0), "r"(A1), "r"(A2), "r"(A3), "r"(B0), "r"(B1))

__device__ __forceinline__ void cvt_hilo(float4 v, uint2& oh, uint2& ol) {
    __nv_bfloat162 h01 = __floats2bfloat162_rn(v.x, v.y);
    __nv_bfloat162 h23 = __floats2bfloat162_rn(v.z, v.w);
    __nv_bfloat162 l01 = __floats2bfloat162_rn(v.x - __bfloat162float(h01.x),
                                               v.y - __bfloat162float(h01.y));
    __nv_bfloat162 l23 = __floats2bfloat162_rn(v.z - __bfloat162float(h23.x),
                                               v.w - __bfloat162float(h23.y));
    oh.x = *(uint32_t*)&h01; oh.y = *(uint32_t*)&h23;
    ol.x = *(uint32_t*)&l01; ol.y = *(uint32_t*)&l23;
}

__global__ void __launch_bounds__(256) mma_pregate(
    const float* __restrict__ A,     // [M][K] fp32
    const float* __restrict__ W,     // [512][K] fp32
    const float* __restrict__ ba, const float* __restrict__ bb,
    float* __restrict__ C,           // [M][512]
    int K)
{
    extern __shared__ __nv_bfloat16 smem[];
    const int stride = K + 8;                    // bf16 elems per row (pad 16B)
    __nv_bfloat16* sAhi = smem;
    __nv_bfloat16* sAlo = sAhi + 128 * stride;
    __nv_bfloat16* sWhi = sAlo + 128 * stride;
    __nv_bfloat16* sWlo = sWhi + 128 * stride;
    float* sbias = (float*)(sWlo + 128 * stride);

    const int tid = threadIdx.x;
    const int lane = tid & 31;
    const int wid = tid >> 5;
    const int wm = wid & 3;              // warp m index: rows wm*32 .. +32
    const int wn = wid >> 2;             // warp n index: cols wn*64 .. +64
    const int g = lane >> 2;             // group id 0..7
    const int tig = lane & 3;            // thread-in-group

    const int m0 = blockIdx.x * 128;
    const int kv = K >> 2;               // float4s per row

    // biases (full 512)
    for (int i = tid; i < 512; i += 256) sbias[i] = ba[i] + bb[i];

    // convert A tile once: 128 rows x K
    for (int idx = tid; idx < 128 * kv; idx += 256) {
        int row = idx / kv;
        int q = idx - row * kv;
        float4 v = *(const float4*)(A + (size_t)(m0 + row) * K + q * 4);
        uint2 oh, ol;
        cvt_hilo(v, oh, ol);
        *(uint2*)(&sAhi[row * stride + q * 4]) = oh;
        *(uint2*)(&sAlo[row * stride + q * 4]) = ol;
    }

    for (int nb = 0; nb < 4; nb++) {
        __syncthreads();   // prior mma done reading W (and A tile ready at nb=0)
        // convert W block: rows nb*128 .. +128
        for (int idx = tid; idx < 128 * kv; idx += 256) {
            int row = idx / kv;
            int q = idx - row * kv;
            float4 v = *(const float4*)(W + (size_t)(nb * 128 + row) * K + q * 4);
            uint2 oh, ol;
            cvt_hilo(v, oh, ol);
            *(uint2*)(&sWhi[row * stride + q * 4]) = oh;
            *(uint2*)(&sWlo[row * stride + q * 4]) = ol;
        }
        __syncthreads();

        float d[2][8][4];
        #pragma unroll
        for (int mf = 0; mf < 2; mf++)
            #pragma unroll
            for (int nf = 0; nf < 8; nf++)
                #pragma unroll
                for (int e = 0; e < 4; e++) d[mf][nf][e] = 0.0f;

        const int nks = K >> 4;
        for (int ks = 0; ks < nks; ks++) {
            const int c0 = ks * 16 + 2 * tig;
            const int c1 = c0 + 8;

            uint32_t AH[2][4], AL[2][4];
            #pragma unroll
            for (int mf = 0; mf < 2; mf++) {
                int r0 = (wm * 32 + mf * 16 + g) * stride;
                int r8 = r0 + 8 * stride;
                AH[mf][0] = *(const uint32_t*)(&sAhi[r0 + c0]);
                AH[mf][1] = *(const uint32_t*)(&sAhi[r8 + c0]);
                AH[mf][2] = *(const uint32_t*)(&sAhi[r0 + c1]);
                AH[mf][3] = *(const uint32_t*)(&sAhi[r8 + c1]);
                AL[mf][0] = *(const uint32_t*)(&sAlo[r0 + c0]);
                AL[mf][1] = *(const uint32_t*)(&sAlo[r8 + c0]);
                AL[mf][2] = *(const uint32_t*)(&sAlo[r0 + c1]);
                AL[mf][3] = *(const uint32_t*)(&sAlo[r8 + c1]);
            }
            #pragma unroll
            for (int nf = 0; nf < 8; nf++) {
                int rb = (wn * 64 + nf * 8 + g) * stride;
                uint32_t BH0 = *(const uint32_t*)(&sWhi[rb + c0]);
                uint32_t BH1 = *(const uint32_t*)(&sWhi[rb + c1]);
                uint32_t BL0 = *(const uint32_t*)(&sWlo[rb + c0]);
                uint32_t BL1 = *(const uint32_t*)(&sWlo[rb + c1]);
                #pragma unroll
                for (int mf = 0; mf < 2; mf++) {
                    MMA_BF16(d[mf][nf], AH[mf][0], AH[mf][1], AH[mf][2], AH[mf][3], BH0, BH1);
                    MMA_BF16(d[mf][nf], AL[mf][0], AL[mf][1], AL[mf][2], AL[mf][3], BH0, BH1);
                    MMA_BF16(d[mf][nf], AH[mf][0], AH[mf][1], AH[mf][2], AH[mf][3], BL0, BL1);
                }
            }
        }

        // epilogue: add bias, store float2 pairs
        #pragma unroll
        for (int mf = 0; mf < 2; mf++) {
            int r0 = wm * 32 + mf * 16 + g;
            #pragma unroll
            for (int nf = 0; nf < 8; nf++) {
                int nl = nb * 128 + wn * 64 + nf * 8 + 2 * tig;
                float bx = sbias[nl];
                float by = sbias[nl + 1];
                float2 o0, o1;
                o0.x = d[mf][nf][0] + bx; o0.y = d[mf][nf][1] + by;
                o1.x = d[mf][nf][2] + bx; o1.y = d[mf][nf][3] + by;
                *(float2*)(C + (size_t)(m0 + r0) * GG + nl) = o0;
                *(float2*)(C + (size_t)(m0 + r0 + 8) * GG + nl) = o1;
            }
        }
    }
}

// -------- LSTM recurrence (round-4, unchanged) --------
#define MAC4(HV0, HV1, HV2, HV3, W0, W1) { \
    a00 = fma2(HV0, W0.x, a00); a01 = fma2(HV0, W0.y, a01); \
    a02 = fma2(HV0, W1.x, a02); a03 = fma2(HV0, W1.y, a03); \
    a10 = fma2(HV1, W0.x, a10); a11 = fma2(HV1, W0.y, a11); \
    a12 = fma2(HV1, W1.x, a12); a13 = fma2(HV1, W1.y, a13); \
    a20 = fma2(HV2, W0.x, a20); a21 = fma2(HV2, W0.y, a21); \
    a22 = fma2(HV2, W1.x, a22); a23 = fma2(HV2, W1.y, a23); \
    a30 = fma2(HV3, W0.x, a30); a31 = fma2(HV3, W0.y, a31); \
    a32 = fma2(HV3, W1.x, a32); a33 = fma2(HV3, W1.y, a33); }

__global__ void __launch_bounds__(512, 1) lstm_layer_kernel(
    const float* __restrict__ xg,
    const float* __restrict__ WTI,
    float* __restrict__ hout,
    float* __restrict__ hlast)
{
    extern __shared__ float sm[];
    const ulonglong2* swA = (const ulonglong2*)sm;
    const ulonglong2* swB = swA + 6144;
    float* sh = sm + 49152;
    float4* sxf = (float4*)(sm + 49152 + 512);

    const int tid = threadIdx.x;
    const int j = tid & 127;
    const int u = tid >> 7;
    const int b0 = blockIdx.x * 4;

    {
        const float4* g4 = (const float4*)WTI;
        float4* s4 = (float4*)sm;
        #pragma unroll 4
        for (int i = tid; i < 6144; i += 512) s4[i] = g4[i];
        #pragma unroll 4
        for (int i = tid; i < 6144; i += 512) s4[6144 + i] = g4[8192 + i];
    }
    ulonglong2 wtA[4], wtB[4];
    {
        const ulonglong2* gA = (const ulonglong2*)WTI;
        const ulonglong2* gB = gA + 8192;
        int kt = KPSM + u * 4;
        #pragma unroll
        for (int i = 0; i < 4; i++) {
            wtA[i] = gA[(size_t)(kt + i) * 128 + j];
            wtB[i] = gB[(size_t)(kt + i) * 128 + j];
        }
    }
    sh[tid] = 0.0f;

    const int klo = u * 24;
    const int kplo = u * 12;

    const size_t xbase = ((size_t)(b0 + u)) * TT * GG + j;
    float* houtP = hout ? hout + ((size_t)(b0 + u)) * TT * HH + j : (float*)0;

    float xc0 = xg[xbase], xc1 = xg[xbase + 128], xc2 = xg[xbase + 256], xc3 = xg[xbase + 384];

    float cc = 0.0f, hh = 0.0f;
    __syncthreads();

    for (int t = 0; t < TT; t++) {
        ull a00 = 0, a01 = 0, a02 = 0, a03 = 0;
        ull a10 = 0, a11 = 0, a12 = 0, a13 = 0;
        ull a20 = 0, a21 = 0, a22 = 0, a23 = 0;
        ull a30 = 0, a31 = 0, a32 = 0, a33 = 0;

        float xn0 = 0, xn1 = 0, xn2 = 0, xn3 = 0;
        if (t + 1 < TT) {
            size_t o = xbase + (size_t)(t + 1) * GG;
            xn0 = xg[o]; xn1 = xg[o + 128]; xn2 = xg[o + 256]; xn3 = xg[o + 384];
        }

        #pragma unroll
        for (int g = 0; g < 6; g++) {
            int kb = klo + g * 4;
            ulonglong2 H0 = *(const ulonglong2*)(sh + kb);
            ulonglong2 H1 = *(const ulonglong2*)(sh + 128 + kb);
            ulonglong2 H2 = *(const ulonglong2*)(sh + 256 + kb);
            ulonglong2 H3 = *(const ulonglong2*)(sh + 384 + kb);
            int kpi = (kplo + g * 2) * 128 + j;
            ulonglong2 w0 = swA[kpi];
            ulonglong2 w1 = swB[kpi];
            MAC4(H0.x, H1.x, H2.x, H3.x, w0, w1);
            ulonglong2 w2 = swA[kpi + 128];
            ulonglong2 w3 = swB[kpi + 128];
            MAC4(H0.y, H1.y, H2.y, H3.y, w2, w3);
        }
        #pragma unroll
        for (int g = 0; g < 2; g++) {
            int kb = 96 + u * 8 + g * 4;
            ulonglong2 H0 = *(const ulonglong2*)(sh + kb);
            ulonglong2 H1 = *(const ulonglong2*)(sh + 128 + kb);
            ulonglong2 H2 = *(const ulonglong2*)(sh + 256 + kb);
            ulonglong2 H3 = *(const ulonglong2*)(sh + 384 + kb);
            MAC4(H0.x, H1.x, H2.x, H3.x, wtA[g * 2], wtB[g * 2]);
            MAC4(H0.y, H1.y, H2.y, H3.y, wtA[g * 2 + 1], wtB[g * 2 + 1]);
        }

        float4 s0, s1, s2, s3;
        s0.x = red2(a00); s0.y = red2(a01); s0.z = red2(a02); s0.w = red2(a03);
        s1.x = red2(a10); s1.y = red2(a11); s1.z = red2(a12); s1.w = red2(a13);
        s2.x = red2(a20); s2.y = red2(a21); s2.z = red2(a22); s2.w = red2(a23);
        s3.x = red2(a30); s3.y = red2(a31); s3.z = red2(a32); s3.w = red2(a33);

        if (u != 0) sxf[(0 * 3 + (u - 1)) * 128 + j] = s0;
        if (u != 1) sxf[(1 * 3 + ((u == 0) ? 0 : u - 1)) * 128 + j] = s1;
        if (u != 2) sxf[(2 * 3 + ((u == 3) ? 2 : u)) * 128 + j] = s2;
        if (u != 3) sxf[(3 * 3 + u) * 128 + j] = s3;
        __syncthreads();
        {
            float4 own = (u == 0) ? s0 : (u == 1) ? s1 : (u == 2) ? s2 : s3;
            float4 p0 = sxf[u * 384 + j];
            float4 p1 = sxf[u * 384 + 128 + j];
            float4 p2 = sxf[u * 384 + 256 + j];
            float gi = own.x + xc0 + p0.x + p1.x + p2.x;
            float gf = own.y + xc1 + p0.y + p1.y + p2.y;
            float gg2 = own.z + xc2 + p0.z + p1.z + p2.z;
            float go = own.w + xc3 + p0.w + p1.w + p2.w;

            float ii = sigf(gi), ff = sigf(gf), g = tanhx(gg2), oo = sigf(go);
            cc = ff * cc + ii * g;
            hh = oo * tanhx(cc);

            sh[u * 128 + j] = hh;
            if (hout) houtP[(size_t)t * HH] = hh;
        }
        xc0 = xn0; xc1 = xn1; xc2 = xn2; xc3 = xn3;
        __syncthreads();
    }

    if (hlast) hlast[(b0 + u) * HH + j] = hh;
}

// -------- MLP head --------
__device__ __forceinline__ float celuf(float x) { return x > 0.0f ? x : expm1f(x); }

__global__ void __launch_bounds__(256) head_kernel(
    const float* __restrict__ hlast,
    const float* __restrict__ W1, const float* __restrict__ b1,
    const float* __restrict__ W2, const float* __restrict__ b2,
    float* __restrict__ out)
{
    const int b = blockIdx.x;
    const int tid = threadIdx.x;
    __shared__ float sl[HH];
    __shared__ float sy[DLL];

    if (tid < HH) sl[tid] = hlast[b * HH + tid];
    __syncthreads();

    float s = b1[tid];
    const float* w = W1 + (size_t)tid * HH;
    #pragma unroll 8
    for (int k = 0; k < HH; k++) s += sl[k] * w[k];
    sy[tid] = celuf(s);
    __syncthreads();

    if (tid < OUTD) {
        float s2 = b2[tid];
        const float* w2 = W2 + (size_t)tid * DLL;
        #pragma unroll 8
        for (int k = 0; k < DLL; k++) s2 += sy[k] * w2[k];
        out[b * OUTD + tid] = celuf(s2);
    }
}

__global__ void zero_tail(float* __restrict__ p, int n) {
    int i = blockIdx.x * 256 + threadIdx.x;
    if (i < n) p[i] = 0.0f;
}

// -------- launch --------
extern "C" void kernel_launch(void* const* d_in, const int* in_sizes, int n_in,
                              void* d_out, int out_size)
{
    const float* x    = (const float*)d_in[0];
    const float* Wih0 = (const float*)d_in[1];
    const float* Whh0 = (const float*)d_in[2];
    const float* bih0 = (const float*)d_in[3];
    const float* bhh0 = (const float*)d_in[4];
    const float* Wih1 = (const float*)d_in[5];
    const float* Whh1 = (const float*)d_in[6];
    const float* bih1 = (const float*)d_in[7];
    const float* bhh1 = (const float*)d_in[8];
    const float* W1   = (const float*)d_in[9];
    const float* b1   = (const float*)d_in[10];
    const float* W2   = (const float*)d_in[11];
    const float* b2   = (const float*)d_in[12];
    float* out = (float*)d_out;

    float *xgp, *h0p, *hlastp, *wt0p, *wt1p;
    cudaGetSymbolAddress((void**)&xgp,    g_xg);
    cudaGetSymbolAddress((void**)&h0p,    g_h0);
    cudaGetSymbolAddress((void**)&hlastp, g_hlast);
    cudaGetSymbolAddress((void**)&wt0p,   g_WT0);
    cudaGetSymbolAddress((void**)&wt1p,   g_WT1);

    // dynamic smem: 4 tiles of 128*(K+8) bf16 + 512-float bias
    const int smem_k128 = 4 * 128 * (HH + 8) * 2 + 512 * 4;      // 141312
    const int smem_k32  = 4 * 128 * (INDIM + 8) * 2 + 512 * 4;   // 42  KB

    cudaFuncSetAttribute(lstm_layer_kernel, cudaFuncAttributeMaxDynamicSharedMemorySize, LSTM_SMEM);
    cudaFuncSetAttribute(mma_pregate,       cudaFuncAttributeMaxDynamicSharedMemorySize, smem_k128);

    prep_whh<<<256, 256>>>(Whh0, wt0p);
    prep_whh<<<256, 256>>>(Whh1, wt1p);

    // layer 0: pre-gates (mma.sync bf16 split, K=32) then recurrence
    mma_pregate<<<M_TOT / 128, 256, smem_k32>>>(x, Wih0, bih0, bhh0, xgp, INDIM);
    lstm_layer_kernel<<<BB / 4, 512, LSTM_SMEM>>>(xgp, wt0p, h0p, nullptr);

    // layer 1: pre-gates (mma.sync bf16 split, K=128) then recurrence
    mma_pregate<<<M_TOT / 128, 256, smem_k128>>>(h0p, Wih1, bih1, bhh1, xgp, HH);
    lstm_layer_kernel<<<BB / 4, 512, LSTM_SMEM>>>(xgp, wt1p, nullptr, hlastp);

    head_kernel<<<BB, 256>>>(hlastp, W1, b1, W2, b2, out);
    int tail = out_size - BB * OUTD;
    if (tail > 0)
        zero_tail<<<(tail + 255) / 256, 256>>>(out + BB * OUTD, tail);
}